// round 2
// baseline (speedup 1.0000x reference)
#include <cuda_runtime.h>
#include <math.h>

#define BB 2048
#define KK 20
#define DD 128
#define TT 100
#define CC 128
#define TKN 40
#define HT 20
#define HC 512

// Scratch (device globals; no runtime allocation allowed)
__device__ float g_tok [(size_t)BB * TKN * CC];
__device__ float g_tok2[(size_t)BB * TKN * CC];

// Packed fp32x2 FMA (Blackwell FFMA2; only reachable via PTX fma.rn.f32x2)
__device__ __forceinline__ float2 ffma2(float2 a, float2 b, float2 c) {
    float2 d;
    asm("fma.rn.f32x2 %0, %1, %2, %3;"
        : "=l"(*reinterpret_cast<unsigned long long*>(&d))
        : "l"(*reinterpret_cast<unsigned long long*>(&a)),
          "l"(*reinterpret_cast<unsigned long long*>(&b)),
          "l"(*reinterpret_cast<unsigned long long*>(&c)));
    return d;
}

__device__ __forceinline__ float gelu_(float x) {
    return 0.5f * x * (1.f + erff(x * 0.7071067811865476f));
}

// ---------------------------------------------------------------------------
// One-hop branch: tokens[b,t,:] = concat(edge_table[eid], tenc(dt,eid)) @ proj_W + b
// 2 rows per 128-thread block; 64 threads per row, each owns a float2 of outputs.
// ---------------------------------------------------------------------------
__global__ __launch_bounds__(128) void k_onehop(
    const float* __restrict__ et,
    const int*   __restrict__ srcI, const int* __restrict__ dstI,
    const float* __restrict__ dts,  const float* __restrict__ dtd,
    const float* __restrict__ tw,   const float* __restrict__ tbv,
    const float* __restrict__ W,    const float* __restrict__ bias)
{
    __shared__ float feat[2][232];
    const int half = threadIdx.x >> 6;
    const int lane = threadIdx.x & 63;
    const int row  = blockIdx.x * 2 + half;
    const int b = row / TKN, t = row % TKN;

    int eid; float dt;
    if (t < KK) { eid = srcI[b*KK + t];        dt = dts[b*KK + t]; }
    else        { eid = dstI[b*KK + t - KK];   dt = dtd[b*KK + t - KK]; }

    const float* er = et + (size_t)eid * DD;
    feat[half][lane]      = er[lane];
    feat[half][lane + 64] = er[lane + 64];
    const float msk = (eid == 0) ? 0.f : 1.f;
    feat[half][DD + lane] = msk * cosf(dt * tw[lane] + tbv[lane]);
    if (lane < TT - 64)
        feat[half][DD + 64 + lane] = msk * cosf(dt * tw[64 + lane] + tbv[64 + lane]);
    __syncthreads();

    const int c0 = lane * 2;
    float2 acc = *(const float2*)&bias[c0];
    const float* fp = feat[half];
    #pragma unroll 4
    for (int f = 0; f < DD + TT; ++f) {
        float2 w = *(const float2*)&W[f * CC + c0];
        float a = fp[f];
        acc = ffma2(make_float2(a, a), w, acc);
    }
    *(float2*)&g_tok[((size_t)b * TKN + t) * CC + c0] = acc;
}

// ---------------------------------------------------------------------------
// Two-hop branch: feat = [e1 | e2 | e | tenc(dt2, e1)] (484) @ eproj_W[j] + eproj_b[j]
// ---------------------------------------------------------------------------
__global__ __launch_bounds__(128) void k_twohop(
    const float* __restrict__ et,
    const int* __restrict__ srcI, const int* __restrict__ dstI,
    const int* __restrict__ s2e1, const int* __restrict__ s2e2,
    const int* __restrict__ d2e1, const int* __restrict__ d2e2,
    const float* __restrict__ dt2s, const float* __restrict__ dt2d,
    const float* __restrict__ tw,   const float* __restrict__ tbv,
    const float* __restrict__ eW,   const float* __restrict__ eb)
{
    __shared__ float feat[2][488];
    const int half = threadIdx.x >> 6;
    const int lane = threadIdx.x & 63;
    const int row  = blockIdx.x * 2 + half;
    const int b = row / TKN, t = row % TKN;

    int e1, e2, e3, j; float dt;
    if (t < KK) { int i = b*KK + t;      e1 = s2e1[i]; e2 = s2e2[i]; e3 = srcI[i]; dt = dt2s[i]; j = 0; }
    else        { int i = b*KK + t - KK; e1 = d2e1[i]; e2 = d2e2[i]; e3 = dstI[i]; dt = dt2d[i]; j = 1; }

    const float* r1 = et + (size_t)e1 * DD;
    const float* r2 = et + (size_t)e2 * DD;
    const float* r3 = et + (size_t)e3 * DD;
    feat[half][lane]            = r1[lane];
    feat[half][lane + 64]       = r1[lane + 64];
    feat[half][128 + lane]      = r2[lane];
    feat[half][128 + lane + 64] = r2[lane + 64];
    feat[half][256 + lane]      = r3[lane];
    feat[half][256 + lane + 64] = r3[lane + 64];
    const float msk = (e1 == 0) ? 0.f : 1.f;
    feat[half][384 + lane] = msk * cosf(dt * tw[lane] + tbv[lane]);
    if (lane < TT - 64)
        feat[half][384 + 64 + lane] = msk * cosf(dt * tw[64 + lane] + tbv[64 + lane]);
    __syncthreads();

    const int F = 3 * DD + TT;  // 484
    const float* W = eW + (size_t)j * F * CC;
    const int c0 = lane * 2;
    float2 acc = *(const float2*)&eb[j * CC + c0];
    const float* fp = feat[half];
    #pragma unroll 4
    for (int f = 0; f < F; ++f) {
        float2 w = *(const float2*)&W[f * CC + c0];
        float a = fp[f];
        acc = ffma2(make_float2(a, a), w, acc);
    }
    *(float2*)&g_tok2[((size_t)b * TKN + t) * CC + c0] = acc;
}

// ---------------------------------------------------------------------------
// Mixer layer: one CTA per sample, all state in shared memory.
// token-mix (LN over 40 + FFN 40->20->40) then channel-mix (LN over 128 + FFN 128->512->128)
// ---------------------------------------------------------------------------
struct MixS {
    float x[TKN][CC];       // 20480 B
    float xln[TKN][CC];     // 20480 B
    float h[TKN][HC];       // 81920 B
    float tw1[TKN * HT];
    float tw2[HT * TKN];
    float tb1[HT], tb2[TKN], tg[TKN], tb[TKN];
    float cg[CC], cb[CC];
    float cb1[HC], cb2[CC];
};

__global__ __launch_bounds__(256, 1) void k_mixer(
    int which, int mi,
    const float* __restrict__ tlng, const float* __restrict__ tlnb,
    const float* __restrict__ tW1,  const float* __restrict__ tB1,
    const float* __restrict__ tW2,  const float* __restrict__ tB2,
    const float* __restrict__ clng, const float* __restrict__ clnb,
    const float* __restrict__ cW1,  const float* __restrict__ cB1,
    const float* __restrict__ cW2,  const float* __restrict__ cB2)
{
    extern __shared__ char raw[];
    MixS& s = *reinterpret_cast<MixS*>(raw);
    const int tid = threadIdx.x;
    float* xg = (which ? g_tok2 : g_tok) + (size_t)blockIdx.x * TKN * CC;

    for (int i = tid; i < TKN * CC / 4; i += 256)
        ((float4*)s.x)[i] = ((const float4*)xg)[i];
    for (int i = tid; i < TKN * HT; i += 256) s.tw1[i] = tW1[mi * TKN * HT + i];
    for (int i = tid; i < HT * TKN; i += 256) s.tw2[i] = tW2[mi * HT * TKN + i];
    for (int i = tid; i < HC; i += 256)       s.cb1[i] = cB1[mi * HC + i];
    if (tid < HT)  s.tb1[tid] = tB1[mi * HT + tid];
    if (tid < TKN) { s.tb2[tid] = tB2[mi*TKN+tid]; s.tg[tid] = tlng[mi*TKN+tid]; s.tb[tid] = tlnb[mi*TKN+tid]; }
    if (tid < CC)  { s.cg[tid] = clng[mi*CC+tid];  s.cb[tid] = clnb[mi*CC+tid];  s.cb2[tid] = cB2[mi*CC+tid]; }
    __syncthreads();

    // ---- token mixing: thread c handles channel c ----
    if (tid < CC) {
        const int c = tid;
        float v[TKN];
        float sum = 0.f;
        #pragma unroll
        for (int t = 0; t < TKN; ++t) { v[t] = s.x[t][c]; sum += v[t]; }
        const float mean = sum * (1.f / TKN);
        float var = 0.f;
        #pragma unroll
        for (int t = 0; t < TKN; ++t) { float d = v[t] - mean; var += d * d; }
        const float rstd = rsqrtf(var * (1.f / TKN) + 1e-5f);
        float h1[HT];
        #pragma unroll
        for (int j = 0; j < HT; ++j) h1[j] = s.tb1[j];
        #pragma unroll
        for (int t = 0; t < TKN; ++t) {
            float a = (v[t] - mean) * rstd * s.tg[t] + s.tb[t];
            #pragma unroll
            for (int j = 0; j < HT; ++j) h1[j] += a * s.tw1[t * HT + j];
        }
        #pragma unroll
        for (int j = 0; j < HT; ++j) h1[j] = gelu_(h1[j]);
        #pragma unroll
        for (int t = 0; t < TKN; ++t) {
            float o = s.tb2[t];
            #pragma unroll
            for (int j = 0; j < HT; ++j) o += h1[j] * s.tw2[j * TKN + t];
            s.x[t][c] = v[t] + o;
        }
    }
    __syncthreads();

    // ---- channel LN -> xln (warp per token) ----
    {
        const int w = tid >> 5, ln = tid & 31;
        for (int t = w; t < TKN; t += 8) {
            float4 xv = *(const float4*)&s.x[t][ln * 4];
            float ssum = xv.x + xv.y + xv.z + xv.w;
            #pragma unroll
            for (int o = 16; o > 0; o >>= 1) ssum += __shfl_xor_sync(0xffffffffu, ssum, o);
            const float mean = ssum * (1.f / CC);
            float dx = xv.x - mean, dy = xv.y - mean, dz = xv.z - mean, dw = xv.w - mean;
            float vs = dx*dx + dy*dy + dz*dz + dw*dw;
            #pragma unroll
            for (int o = 16; o > 0; o >>= 1) vs += __shfl_xor_sync(0xffffffffu, vs, o);
            const float rstd = rsqrtf(vs * (1.f / CC) + 1e-5f);
            const int c = ln * 4;
            float4 out;
            out.x = dx * rstd * s.cg[c+0] + s.cb[c+0];
            out.y = dy * rstd * s.cg[c+1] + s.cb[c+1];
            out.z = dz * rstd * s.cg[c+2] + s.cb[c+2];
            out.w = dw * rstd * s.cg[c+3] + s.cb[c+3];
            *(float4*)&s.xln[t][c] = out;
        }
    }
    __syncthreads();

    // ---- GEMM1: h = gelu(xln[40,128] @ cW1[128,512] + cb1) ----
    // thread owns 4 j-columns (2 f32x2) x 20 tokens; FFMA2:LDS = 2:1
    {
        const int jq = tid & 127, th = tid >> 7;
        const int j0 = jq * 4, t0 = th * 20;
        const float* Wp = cW1 + (size_t)mi * CC * HC;
        float2 a0[20], a1[20];
        const float2 b01 = make_float2(s.cb1[j0],     s.cb1[j0 + 1]);
        const float2 b23 = make_float2(s.cb1[j0 + 2], s.cb1[j0 + 3]);
        #pragma unroll
        for (int t = 0; t < 20; ++t) { a0[t] = b01; a1[t] = b23; }
        #pragma unroll 2
        for (int c = 0; c < CC; ++c) {
            float4 w = *(const float4*)&Wp[(size_t)c * HC + j0];
            float2 w01 = make_float2(w.x, w.y), w23 = make_float2(w.z, w.w);
            #pragma unroll
            for (int t = 0; t < 20; ++t) {
                float a = s.xln[t0 + t][c];
                float2 ad = make_float2(a, a);
                a0[t] = ffma2(ad, w01, a0[t]);
                a1[t] = ffma2(ad, w23, a1[t]);
            }
        }
        #pragma unroll
        for (int t = 0; t < 20; ++t) {
            float4 o;
            o.x = gelu_(a0[t].x); o.y = gelu_(a0[t].y);
            o.z = gelu_(a1[t].x); o.w = gelu_(a1[t].y);
            *(float4*)&s.h[t0 + t][j0] = o;
        }
    }
    __syncthreads();

    // ---- GEMM2: x += h[40,512] @ cW2[512,128] + cb2 ----
    // thread owns 4 c-columns x 5 tokens; FFMA2:LDS = 2:1
    {
        const int cq = tid & 31, tg = tid >> 5;
        const int c0 = cq * 4, t0 = tg * 5;
        const float* Wp = cW2 + (size_t)mi * HC * CC;
        float2 a0[5], a1[5];
        const float2 b01 = make_float2(s.cb2[c0],     s.cb2[c0 + 1]);
        const float2 b23 = make_float2(s.cb2[c0 + 2], s.cb2[c0 + 3]);
        #pragma unroll
        for (int t = 0; t < 5; ++t) { a0[t] = b01; a1[t] = b23; }
        #pragma unroll 4
        for (int j = 0; j < HC; ++j) {
            float4 w = *(const float4*)&Wp[(size_t)j * CC + c0];
            float2 w01 = make_float2(w.x, w.y), w23 = make_float2(w.z, w.w);
            #pragma unroll
            for (int t = 0; t < 5; ++t) {
                float a = s.h[t0 + t][j];
                float2 ad = make_float2(a, a);
                a0[t] = ffma2(ad, w01, a0[t]);
                a1[t] = ffma2(ad, w23, a1[t]);
            }
        }
        #pragma unroll
        for (int t = 0; t < 5; ++t) {
            float4 xv = *(const float4*)&s.x[t0 + t][c0];
            xv.x += a0[t].x; xv.y += a0[t].y; xv.z += a1[t].x; xv.w += a1[t].y;
            *(float4*)&s.x[t0 + t][c0] = xv;
        }
    }
    __syncthreads();

    for (int i = tid; i < TKN * CC / 4; i += 256)
        ((float4*)xg)[i] = ((const float4*)s.x)[i];
}

// ---------------------------------------------------------------------------
// Mean over tokens + pcc-softmax combine
// ---------------------------------------------------------------------------
__global__ __launch_bounds__(128) void k_comb(
    const float* __restrict__ p1, const float* __restrict__ p2, float* __restrict__ out)
{
    const int b = blockIdx.x, c = threadIdx.x;
    const float* t1 = g_tok  + (size_t)b * TKN * CC + c;
    const float* t2 = g_tok2 + (size_t)b * TKN * CC + c;
    float s1 = 0.f, s2 = 0.f;
    #pragma unroll
    for (int t = 0; t < TKN; ++t) { s1 += t1[(size_t)t * CC]; s2 += t2[(size_t)t * CC]; }
    s1 *= (1.f / TKN); s2 *= (1.f / TKN);
    const float a = p1[b], bb = p2[b];
    const float mx = fmaxf(a, bb);
    const float e1 = expf(a - mx), e2 = expf(bb - mx);
    out[(size_t)b * CC + c] = (e1 * s1 + e2 * s2) / (e1 + e2);
}

// ---------------------------------------------------------------------------
extern "C" void kernel_launch(void* const* d_in, const int* in_sizes, int n_in,
                              void* d_out, int out_size)
{
    (void)in_sizes; (void)n_in; (void)out_size;
    const float* et   = (const float*)d_in[0];
    const int*   srcI = (const int*)d_in[1];
    const int*   dstI = (const int*)d_in[2];
    const int*   s2e1 = (const int*)d_in[3];
    const int*   s2e2 = (const int*)d_in[4];
    const int*   d2e1 = (const int*)d_in[5];
    const int*   d2e2 = (const int*)d_in[6];
    const float* dts  = (const float*)d_in[7];
    const float* dtd  = (const float*)d_in[8];
    const float* dt2s = (const float*)d_in[9];
    const float* dt2d = (const float*)d_in[10];
    const float* pcc1 = (const float*)d_in[11];
    const float* pcc2 = (const float*)d_in[12];
    const float* tw   = (const float*)d_in[13];
    const float* tb   = (const float*)d_in[14];
    const float* pW   = (const float*)d_in[15];
    const float* pB   = (const float*)d_in[16];
    const float* eW   = (const float*)d_in[17];
    const float* eB   = (const float*)d_in[18];
    const float* tlng = (const float*)d_in[19];
    const float* tlnb = (const float*)d_in[20];
    const float* tW1  = (const float*)d_in[21];
    const float* tB1  = (const float*)d_in[22];
    const float* tW2  = (const float*)d_in[23];
    const float* tB2  = (const float*)d_in[24];
    const float* clng = (const float*)d_in[25];
    const float* clnb = (const float*)d_in[26];
    const float* cW1  = (const float*)d_in[27];
    const float* cB1  = (const float*)d_in[28];
    const float* cW2  = (const float*)d_in[29];
    const float* cB2  = (const float*)d_in[30];
    float* out = (float*)d_out;

    cudaFuncSetAttribute(k_mixer, cudaFuncAttributeMaxDynamicSharedMemorySize, (int)sizeof(MixS));

    k_onehop<<<BB * TKN / 2, 128>>>(et, srcI, dstI, dts, dtd, tw, tb, pW, pB);
    k_twohop<<<BB * TKN / 2, 128>>>(et, srcI, dstI, s2e1, s2e2, d2e1, d2e2, dt2s, dt2d, tw, tb, eW, eB);
    for (int i = 0; i < 2; ++i)
        k_mixer<<<BB, 256, (int)sizeof(MixS)>>>(0, i,     tlng, tlnb, tW1, tB1, tW2, tB2, clng, clnb, cW1, cB1, cW2, cB2);
    for (int i = 0; i < 2; ++i)
        k_mixer<<<BB, 256, (int)sizeof(MixS)>>>(1, 2 + i, tlng, tlnb, tW1, tB1, tW2, tB2, clng, clnb, cW1, cB1, cW2, cB2);
    k_comb<<<BB, 128>>>(pcc1, pcc2, out);
}

// round 3
// speedup vs baseline: 2.1032x; 2.1032x over previous
#include <cuda_runtime.h>
#include <math.h>

#define BB 2048
#define KK 20
#define DD 128
#define TT 100
#define CC 128
#define TKN 40
#define HT 20
#define HC 512
#define XTS 44
#define HTS 44
#define H1S 21
#define FTS 36

__device__ float g_tok [(size_t)BB * TKN * CC];
__device__ float g_tok2[(size_t)BB * TKN * CC];
__device__ float g_S1 [4 * HC];
__device__ float g_B1p[4 * HC];

__device__ __forceinline__ float2 ffma2(float2 a, float2 b, float2 c) {
    float2 d;
    asm("fma.rn.f32x2 %0, %1, %2, %3;"
        : "=l"(*reinterpret_cast<unsigned long long*>(&d))
        : "l"(*reinterpret_cast<unsigned long long*>(&a)),
          "l"(*reinterpret_cast<unsigned long long*>(&b)),
          "l"(*reinterpret_cast<unsigned long long*>(&c)));
    return d;
}
__device__ __forceinline__ float2 mkf2(float x, float y) { float2 r; r.x = x; r.y = y; return r; }
__device__ __forceinline__ float gelu_(float x) {
    return 0.5f * x * (1.f + erff(x * 0.7071067811865476f));
}

// ---- fold channel-LN gamma/beta into GEMM1 ----
__global__ __launch_bounds__(256) void k_prep(
    const float* __restrict__ cW1, const float* __restrict__ cB1,
    const float* __restrict__ clng, const float* __restrict__ clnb)
{
    const int idx = blockIdx.x * 256 + threadIdx.x;   // 4*512
    const int mi = idx >> 9, j = idx & 511;
    const float* W = cW1 + (size_t)mi * CC * HC;
    float s1 = 0.f, t1 = 0.f;
    #pragma unroll 4
    for (int c = 0; c < CC; ++c) {
        float w = W[c * HC + j];
        s1 = fmaf(clng[mi * CC + c], w, s1);
        t1 = fmaf(clnb[mi * CC + c], w, t1);
    }
    g_S1[idx]  = s1;
    g_B1p[idx] = t1 + cB1[mi * HC + j];
}

// ---- projections: 32 rows per 128-thread CTA ----
__global__ __launch_bounds__(128) void k_proj(
    const float* __restrict__ et,
    const int* __restrict__ srcI, const int* __restrict__ dstI,
    const int* __restrict__ s2e1, const int* __restrict__ s2e2,
    const int* __restrict__ d2e1, const int* __restrict__ d2e2,
    const float* __restrict__ dts,  const float* __restrict__ dtd,
    const float* __restrict__ dt2s, const float* __restrict__ dt2d,
    const float* __restrict__ tw,   const float* __restrict__ tbv,
    const float* __restrict__ pW,   const float* __restrict__ pB,
    const float* __restrict__ eW,   const float* __restrict__ eb)
{
    extern __shared__ float featT[];   // [F][FTS]
    const int tid = threadIdx.x;
    const int lane = tid & 31, w = tid >> 5;
    const int bid = blockIdx.x;

    int kind, jside = 0, rowbase;
    if (bid < 2560)      { kind = 0; rowbase = bid * 32; }
    else if (bid < 3840) { kind = 1; jside = 0; rowbase = (bid - 2560) * 32; }
    else                 { kind = 1; jside = 1; rowbase = (bid - 3840) * 32; }
    const int F = kind ? (3 * DD + TT) : (DD + TT);

    for (int r8 = 0; r8 < 8; ++r8) {
        const int r = w * 8 + r8;
        const int g = rowbase + r;
        if (kind == 0) {
            const int b = g / TKN, t = g % TKN;
            int eid; float dt;
            if (t < KK) { eid = srcI[b*KK + t];      dt = dts[b*KK + t]; }
            else        { eid = dstI[b*KK + t - KK]; dt = dtd[b*KK + t - KK]; }
            const float* E = et + (size_t)eid * DD;
            const float msk = (eid == 0) ? 0.f : 1.f;
            #pragma unroll
            for (int i = 0; i < 4; ++i) {
                const int f = lane + 32 * i;
                featT[f * FTS + r] = E[f];
                if (f < TT) featT[(DD + f) * FTS + r] = msk * cosf(dt * tw[f] + tbv[f]);
            }
        } else {
            const int b = g / KK, k = g % KK;
            const int i0 = b * KK + k;
            int e1, e2, e3; float dt;
            if (jside == 0) { e1 = s2e1[i0]; e2 = s2e2[i0]; e3 = srcI[i0]; dt = dt2s[i0]; }
            else            { e1 = d2e1[i0]; e2 = d2e2[i0]; e3 = dstI[i0]; dt = dt2d[i0]; }
            const float* E1 = et + (size_t)e1 * DD;
            const float* E2 = et + (size_t)e2 * DD;
            const float* E3 = et + (size_t)e3 * DD;
            const float msk = (e1 == 0) ? 0.f : 1.f;
            #pragma unroll
            for (int i = 0; i < 4; ++i) {
                const int f = lane + 32 * i;
                featT[f * FTS + r]          = E1[f];
                featT[(DD + f) * FTS + r]   = E2[f];
                featT[(2*DD + f) * FTS + r] = E3[f];
                if (f < TT) featT[(3*DD + f) * FTS + r] = msk * cosf(dt * tw[f] + tbv[f]);
            }
        }
    }
    __syncthreads();

    const int cq = tid & 31, rg = tid >> 5;
    const int c0 = cq * 4, r0 = rg * 8;
    const float* W = kind ? (eW + (size_t)jside * F * CC) : pW;

    float2 a0[8], a1[8];
    #pragma unroll
    for (int rr = 0; rr < 8; ++rr) { a0[rr] = mkf2(0.f, 0.f); a1[rr] = mkf2(0.f, 0.f); }

    #pragma unroll 2
    for (int f = 0; f < F; ++f) {
        float4 wv = *(const float4*)&W[(size_t)f * CC + c0];
        float2 w01 = mkf2(wv.x, wv.y), w23 = mkf2(wv.z, wv.w);
        float4 fa = *(const float4*)&featT[f * FTS + r0];
        float4 fb = *(const float4*)&featT[f * FTS + r0 + 4];
        float av[8] = {fa.x, fa.y, fa.z, fa.w, fb.x, fb.y, fb.z, fb.w};
        #pragma unroll
        for (int rr = 0; rr < 8; ++rr) {
            float2 ad = mkf2(av[rr], av[rr]);
            a0[rr] = ffma2(ad, w01, a0[rr]);
            a1[rr] = ffma2(ad, w23, a1[rr]);
        }
    }

    float4 bv = kind ? *(const float4*)&eb[jside * CC + c0] : *(const float4*)&pB[c0];
    #pragma unroll
    for (int rr = 0; rr < 8; ++rr) {
        const int g = rowbase + r0 + rr;
        int b, t; float* outp;
        if (kind == 0) { b = g / TKN; t = g % TKN; outp = g_tok; }
        else           { b = g / KK;  t = (g % KK) + jside * KK; outp = g_tok2; }
        float4 o;
        o.x = a0[rr].x + bv.x; o.y = a0[rr].y + bv.y;
        o.z = a1[rr].x + bv.z; o.w = a1[rr].y + bv.w;
        *(float4*)&outp[((size_t)b * TKN + t) * CC + c0] = o;
    }
}

// ---- mixer: one 640-thread CTA per (branch, sample), loops 2 layers ----
struct MixS {
    float x[TKN * CC];
    float xT[CC * XTS];
    float hT[HC * HTS];     // reused as P[4][TKN*CC] for GEMM2 partials
    float H1[CC * H1S];
    float tw1[TKN * HT], tw2[HT * TKN];
    float S1[HC], B1p[HC];
    float tb1[32], tb2[TKN], tg[TKN], tbe[TKN];
    float cg[CC], cb2s[CC];
    float tm[CC], tr[CC], cm[TKN], cr[TKN];
};

__global__ __launch_bounds__(640, 1) void k_mixer(
    const float* __restrict__ tlng, const float* __restrict__ tlnb,
    const float* __restrict__ tW1,  const float* __restrict__ tB1,
    const float* __restrict__ tW2,  const float* __restrict__ tB2,
    const float* __restrict__ clng,
    const float* __restrict__ cW1,  const float* __restrict__ cW2,
    const float* __restrict__ cB2)
{
    extern __shared__ char raw[];
    MixS& s = *reinterpret_cast<MixS*>(raw);
    const int tid = threadIdx.x;
    const int which = blockIdx.x >> 11;
    const int b = blockIdx.x & 2047;
    float* xg = (which ? g_tok2 : g_tok) + (size_t)b * TKN * CC;

    for (int i = tid; i < TKN * CC / 4; i += 640)
        ((float4*)s.x)[i] = ((const float4*)xg)[i];

    for (int layer = 0; layer < 2; ++layer) {
        const int mi = which * 2 + layer;
        for (int i = tid; i < TKN * HT; i += 640) {
            s.tw1[i] = tW1[mi * TKN * HT + i];
            s.tw2[i] = tW2[mi * HT * TKN + i];
        }
        for (int i = tid; i < HC; i += 640) {
            s.S1[i]  = g_S1[mi * HC + i];
            s.B1p[i] = g_B1p[mi * HC + i];
        }
        if (tid < HT) s.tb1[tid] = tB1[mi * HT + tid];
        if (tid >= 32 && tid < 32 + TKN) {
            int t = tid - 32;
            s.tb2[t] = tB2[mi*TKN+t]; s.tg[t] = tlng[mi*TKN+t]; s.tbe[t] = tlnb[mi*TKN+t];
        }
        if (tid >= 128 && tid < 256) {
            int c = tid - 128;
            s.cg[c] = clng[mi*CC+c]; s.cb2s[c] = cB2[mi*CC+c];
        }
        __syncthreads();

        // A: token-axis LN stats (per channel)
        if (tid < CC) {
            const int c = tid;
            float sum = 0.f;
            #pragma unroll 8
            for (int t = 0; t < TKN; ++t) sum += s.x[t*CC + c];
            const float mean = sum * (1.f / TKN);
            float var = 0.f;
            #pragma unroll 8
            for (int t = 0; t < TKN; ++t) { float d = s.x[t*CC + c] - mean; var += d * d; }
            s.tm[c] = mean;
            s.tr[c] = rsqrtf(var * (1.f / TKN) + 1e-5f);
        }
        __syncthreads();

        // B: token FFN-1 -> H1[c][j] (gelu)
        {
            const int c = tid & 127, jg = tid >> 7;
            const int j0 = jg * 4;
            float2 A0 = mkf2(s.tb1[j0],   s.tb1[j0+1]);
            float2 A1 = mkf2(s.tb1[j0+2], s.tb1[j0+3]);
            const float mean = s.tm[c], rs = s.tr[c];
            #pragma unroll 4
            for (int t = 0; t < TKN; ++t) {
                float a = fmaf((s.x[t*CC + c] - mean) * rs, s.tg[t], s.tbe[t]);
                float4 wv = *(const float4*)&s.tw1[t * HT + j0];
                float2 ad = mkf2(a, a);
                A0 = ffma2(ad, mkf2(wv.x, wv.y), A0);
                A1 = ffma2(ad, mkf2(wv.z, wv.w), A1);
            }
            s.H1[c*H1S + j0+0] = gelu_(A0.x);
            s.H1[c*H1S + j0+1] = gelu_(A0.y);
            s.H1[c*H1S + j0+2] = gelu_(A1.x);
            s.H1[c*H1S + j0+3] = gelu_(A1.y);
        }
        __syncthreads();

        // C: token FFN-2 + residual -> x
        {
            const int c = tid & 127, tg5 = tid >> 7;
            const int t0 = tg5 * 8;
            float2 A0 = mkf2(s.tb2[t0+0], s.tb2[t0+1]);
            float2 A1 = mkf2(s.tb2[t0+2], s.tb2[t0+3]);
            float2 A2 = mkf2(s.tb2[t0+4], s.tb2[t0+5]);
            float2 A3 = mkf2(s.tb2[t0+6], s.tb2[t0+7]);
            #pragma unroll 4
            for (int j = 0; j < HT; ++j) {
                float h = s.H1[c*H1S + j];
                float2 hh = mkf2(h, h);
                float4 wA = *(const float4*)&s.tw2[j*TKN + t0];
                float4 wB = *(const float4*)&s.tw2[j*TKN + t0 + 4];
                A0 = ffma2(hh, mkf2(wA.x, wA.y), A0);
                A1 = ffma2(hh, mkf2(wA.z, wA.w), A1);
                A2 = ffma2(hh, mkf2(wB.x, wB.y), A2);
                A3 = ffma2(hh, mkf2(wB.z, wB.w), A3);
            }
            s.x[(t0+0)*CC + c] += A0.x;  s.x[(t0+1)*CC + c] += A0.y;
            s.x[(t0+2)*CC + c] += A1.x;  s.x[(t0+3)*CC + c] += A1.y;
            s.x[(t0+4)*CC + c] += A2.x;  s.x[(t0+5)*CC + c] += A2.y;
            s.x[(t0+6)*CC + c] += A3.x;  s.x[(t0+7)*CC + c] += A3.y;
        }
        __syncthreads();

        // D1: channel-LN stats (half-warp per token)
        {
            const int w20 = tid >> 5, lane = tid & 31;
            const int t = w20 * 2 + (lane >> 4);
            const int l16 = lane & 15;
            const float* xr = &s.x[t*CC + l16*8];
            float4 va = *(const float4*)xr;
            float4 vb = *(const float4*)(xr + 4);
            float sum = va.x+va.y+va.z+va.w + vb.x+vb.y+vb.z+vb.w;
            #pragma unroll
            for (int o = 8; o > 0; o >>= 1) sum += __shfl_xor_sync(0xffffffffu, sum, o);
            const float mean = sum * (1.f / CC);
            float d0=va.x-mean, d1=va.y-mean, d2=va.z-mean, d3=va.w-mean;
            float d4=vb.x-mean, d5=vb.y-mean, d6=vb.z-mean, d7=vb.w-mean;
            float vs = d0*d0+d1*d1+d2*d2+d3*d3+d4*d4+d5*d5+d6*d6+d7*d7;
            #pragma unroll
            for (int o = 8; o > 0; o >>= 1) vs += __shfl_xor_sync(0xffffffffu, vs, o);
            if (l16 == 0) {
                s.cm[t] = mean;
                s.cr[t] = rsqrtf(vs * (1.f / CC) + 1e-5f);
            }
        }
        // D2: scaled transpose xT[c][t] = x[t][c] * gamma[c]
        {
            const int c = tid & 127, tg5 = tid >> 7;
            const int t0 = tg5 * 8;
            const float gc = s.cg[c];
            float v[8];
            #pragma unroll
            for (int i = 0; i < 8; ++i) v[i] = s.x[(t0+i)*CC + c] * gc;
            float4 pa, pb;
            pa.x=v[0]; pa.y=v[1]; pa.z=v[2]; pa.w=v[3];
            pb.x=v[4]; pb.y=v[5]; pb.z=v[6]; pb.w=v[7];
            *(float4*)&s.xT[c*XTS + t0]     = pa;
            *(float4*)&s.xT[c*XTS + t0 + 4] = pb;
        }
        __syncthreads();

        // E: channel GEMM1 (K=128) with folded LN, gelu -> hT[j][t]
        {
            const int jq = tid & 127, tg5 = tid >> 7;
            const int j0 = jq * 4, t0 = tg5 * 8;
            float2 a0[8], a1[8];
            #pragma unroll
            for (int tt = 0; tt < 8; ++tt) { a0[tt] = mkf2(0.f,0.f); a1[tt] = mkf2(0.f,0.f); }
            const float* W = cW1 + (size_t)mi * CC * HC;
            #pragma unroll 2
            for (int c = 0; c < CC; ++c) {
                float4 wv = *(const float4*)&W[(size_t)c * HC + j0];
                float2 w01 = mkf2(wv.x, wv.y), w23 = mkf2(wv.z, wv.w);
                float4 xa = *(const float4*)&s.xT[c*XTS + t0];
                float4 xb = *(const float4*)&s.xT[c*XTS + t0 + 4];
                float av[8] = {xa.x, xa.y, xa.z, xa.w, xb.x, xb.y, xb.z, xb.w};
                #pragma unroll
                for (int tt = 0; tt < 8; ++tt) {
                    float2 ad = mkf2(av[tt], av[tt]);
                    a0[tt] = ffma2(ad, w01, a0[tt]);
                    a1[tt] = ffma2(ad, w23, a1[tt]);
                }
            }
            const float s10 = s.S1[j0+0], s11 = s.S1[j0+1], s12 = s.S1[j0+2], s13 = s.S1[j0+3];
            const float bp0 = s.B1p[j0+0], bp1 = s.B1p[j0+1], bp2 = s.B1p[j0+2], bp3 = s.B1p[j0+3];
            float hv[4][8];
            #pragma unroll
            for (int tt = 0; tt < 8; ++tt) {
                const int t = t0 + tt;
                const float rv = s.cr[t], mrv = -rv * s.cm[t];
                hv[0][tt] = gelu_(fmaf(rv, a0[tt].x, fmaf(mrv, s10, bp0)));
                hv[1][tt] = gelu_(fmaf(rv, a0[tt].y, fmaf(mrv, s11, bp1)));
                hv[2][tt] = gelu_(fmaf(rv, a1[tt].x, fmaf(mrv, s12, bp2)));
                hv[3][tt] = gelu_(fmaf(rv, a1[tt].y, fmaf(mrv, s13, bp3)));
            }
            #pragma unroll
            for (int jj = 0; jj < 4; ++jj) {
                float4 pa, pb;
                pa.x = hv[jj][0]; pa.y = hv[jj][1]; pa.z = hv[jj][2]; pa.w = hv[jj][3];
                pb.x = hv[jj][4]; pb.y = hv[jj][5]; pb.z = hv[jj][6]; pb.w = hv[jj][7];
                *(float4*)&s.hT[(j0+jj)*HTS + t0]     = pa;
                *(float4*)&s.hT[(j0+jj)*HTS + t0 + 4] = pb;
            }
        }
        __syncthreads();

        // F: channel GEMM2 (K=512) split 4-way over K
        {
            const int kidx = tid / 160;
            const int rr = tid - kidx * 160;
            const int cq = rr & 31, tg5 = rr >> 5;
            const int c0 = cq * 4, t0 = tg5 * 8, jb = kidx * 128;
            float2 b0[8], b1[8];
            #pragma unroll
            for (int tt = 0; tt < 8; ++tt) { b0[tt] = mkf2(0.f,0.f); b1[tt] = mkf2(0.f,0.f); }
            const float* W2 = cW2 + (size_t)mi * HC * CC + (size_t)jb * CC;
            #pragma unroll 2
            for (int jj = 0; jj < 128; ++jj) {
                float4 wv = *(const float4*)&W2[(size_t)jj * CC + c0];
                float2 w01 = mkf2(wv.x, wv.y), w23 = mkf2(wv.z, wv.w);
                float4 ha = *(const float4*)&s.hT[(jb+jj)*HTS + t0];
                float4 hb = *(const float4*)&s.hT[(jb+jj)*HTS + t0 + 4];
                float hvv[8] = {ha.x, ha.y, ha.z, ha.w, hb.x, hb.y, hb.z, hb.w};
                #pragma unroll
                for (int tt = 0; tt < 8; ++tt) {
                    float2 hd = mkf2(hvv[tt], hvv[tt]);
                    b0[tt] = ffma2(hd, w01, b0[tt]);
                    b1[tt] = ffma2(hd, w23, b1[tt]);
                }
            }
            __syncthreads();   // hT reads done before overwriting as partial buffer
            float* P = s.hT;
            #pragma unroll
            for (int tt = 0; tt < 8; ++tt) {
                float4 pv;
                pv.x = b0[tt].x; pv.y = b0[tt].y; pv.z = b1[tt].x; pv.w = b1[tt].y;
                *(float4*)&P[kidx * (TKN*CC) + (t0+tt)*CC + c0] = pv;
            }
        }
        __syncthreads();

        // G: reduce K-split partials + bias + residual -> x
        {
            const int f0 = tid * 8;
            const int c0 = f0 & 127;
            const float* P = s.hT;
            float4 r0 = make_float4(0.f,0.f,0.f,0.f);
            float4 r1 = make_float4(0.f,0.f,0.f,0.f);
            #pragma unroll
            for (int k = 0; k < 4; ++k) {
                float4 pa = *(const float4*)&P[k*(TKN*CC) + f0];
                float4 pb = *(const float4*)&P[k*(TKN*CC) + f0 + 4];
                r0.x += pa.x; r0.y += pa.y; r0.z += pa.z; r0.w += pa.w;
                r1.x += pb.x; r1.y += pb.y; r1.z += pb.z; r1.w += pb.w;
            }
            float4 xa = *(const float4*)&s.x[f0];
            float4 xb = *(const float4*)&s.x[f0 + 4];
            xa.x += r0.x + s.cb2s[c0+0]; xa.y += r0.y + s.cb2s[c0+1];
            xa.z += r0.z + s.cb2s[c0+2]; xa.w += r0.w + s.cb2s[c0+3];
            xb.x += r1.x + s.cb2s[c0+4]; xb.y += r1.y + s.cb2s[c0+5];
            xb.z += r1.z + s.cb2s[c0+6]; xb.w += r1.w + s.cb2s[c0+7];
            *(float4*)&s.x[f0]     = xa;
            *(float4*)&s.x[f0 + 4] = xb;
        }
        __syncthreads();
    }

    for (int i = tid; i < TKN * CC / 4; i += 640)
        ((float4*)xg)[i] = ((const float4*)s.x)[i];
}

// ---- mean over tokens + pcc-softmax combine ----
__global__ __launch_bounds__(128) void k_comb(
    const float* __restrict__ p1, const float* __restrict__ p2, float* __restrict__ out)
{
    const int b = blockIdx.x, c = threadIdx.x;
    const float* t1 = g_tok  + (size_t)b * TKN * CC + c;
    const float* t2 = g_tok2 + (size_t)b * TKN * CC + c;
    float s1 = 0.f, s2 = 0.f;
    #pragma unroll
    for (int t = 0; t < TKN; ++t) { s1 += t1[(size_t)t * CC]; s2 += t2[(size_t)t * CC]; }
    s1 *= (1.f / TKN); s2 *= (1.f / TKN);
    const float a = p1[b], bb = p2[b];
    const float mx = fmaxf(a, bb);
    const float e1 = expf(a - mx), e2 = expf(bb - mx);
    out[(size_t)b * CC + c] = (e1 * s1 + e2 * s2) / (e1 + e2);
}

extern "C" void kernel_launch(void* const* d_in, const int* in_sizes, int n_in,
                              void* d_out, int out_size)
{
    (void)in_sizes; (void)n_in; (void)out_size;
    const float* et   = (const float*)d_in[0];
    const int*   srcI = (const int*)d_in[1];
    const int*   dstI = (const int*)d_in[2];
    const int*   s2e1 = (const int*)d_in[3];
    const int*   s2e2 = (const int*)d_in[4];
    const int*   d2e1 = (const int*)d_in[5];
    const int*   d2e2 = (const int*)d_in[6];
    const float* dts  = (const float*)d_in[7];
    const float* dtd  = (const float*)d_in[8];
    const float* dt2s = (const float*)d_in[9];
    const float* dt2d = (const float*)d_in[10];
    const float* pcc1 = (const float*)d_in[11];
    const float* pcc2 = (const float*)d_in[12];
    const float* tw   = (const float*)d_in[13];
    const float* tb   = (const float*)d_in[14];
    const float* pW   = (const float*)d_in[15];
    const float* pB   = (const float*)d_in[16];
    const float* eW   = (const float*)d_in[17];
    const float* eB   = (const float*)d_in[18];
    const float* tlng = (const float*)d_in[19];
    const float* tlnb = (const float*)d_in[20];
    const float* tW1  = (const float*)d_in[21];
    const float* tB1  = (const float*)d_in[22];
    const float* tW2  = (const float*)d_in[23];
    const float* tB2  = (const float*)d_in[24];
    const float* clng = (const float*)d_in[25];
    const float* clnb = (const float*)d_in[26];
    const float* cW1  = (const float*)d_in[27];
    const float* cB1  = (const float*)d_in[28];
    const float* cW2  = (const float*)d_in[29];
    const float* cB2  = (const float*)d_in[30];
    float* out = (float*)d_out;

    static int inited = 0;
    if (!inited) {
        cudaFuncSetAttribute(k_mixer, cudaFuncAttributeMaxDynamicSharedMemorySize, (int)sizeof(MixS));
        cudaFuncSetAttribute(k_proj,  cudaFuncAttributeMaxDynamicSharedMemorySize, 484 * FTS * 4);
        inited = 1;
    }

    k_prep<<<8, 256>>>(cW1, cB1, clng, clnb);
    k_proj<<<5120, 128, 484 * FTS * 4>>>(et, srcI, dstI, s2e1, s2e2, d2e1, d2e2,
                                         dts, dtd, dt2s, dt2d, tw, tb, pW, pB, eW, eB);
    k_mixer<<<4096, 640, (int)sizeof(MixS)>>>(tlng, tlnb, tW1, tB1, tW2, tB2,
                                              clng, cW1, cW2, cB2);
    k_comb<<<2048, 128>>>(pcc1, pcc2, out);
}